// round 15
// baseline (speedup 1.0000x reference)
#include <cuda_runtime.h>
#include <cuda_bf16.h>
#include <math.h>
#include <stdint.h>

#define NN 384
#define DD 512
#define HH 8
#define FF 64
#define SPL 6

typedef unsigned long long ull;

// ---- scratch (no allocations allowed) ----
__device__ float d_gl[NN * DD];
__device__ float d_gr[NN * DD];
__device__ float d_x1[NN * DD];
__device__ float d_rvec[HH * NN];
__device__ float d_lvec[HH * NN];
__device__ float d_part[SPL * NN * DD];
__device__ float d_pm[SPL * HH * NN];
__device__ float d_ps[SPL * HH * NN];
// bf16 hi/lo operand storage
__device__ __nv_bfloat16 d_wbh[4 * DD * DD];
__device__ __nv_bfloat16 d_wbl[4 * DD * DD];
__device__ __nv_bfloat16 d_xbh[2 * NN * DD];
__device__ __nv_bfloat16 d_xbl[2 * NN * DD];

// ---- PDL helpers ----
__device__ __forceinline__ void pdl_trigger() {
    asm volatile("griddepcontrol.launch_dependents;");
}
__device__ __forceinline__ void pdl_wait() {
    asm volatile("griddepcontrol.wait;" ::: "memory");
}

// ---- packed f32x2 helpers ----
__device__ __forceinline__ ull f2add(ull a, ull b) {
    ull r; asm("add.rn.f32x2 %0, %1, %2;" : "=l"(r) : "l"(a), "l"(b)); return r;
}
__device__ __forceinline__ ull f2fma(ull a, ull b, ull c) {
    ull r; asm("fma.rn.f32x2 %0, %1, %2, %3;" : "=l"(r) : "l"(a), "l"(b), "l"(c)); return r;
}
__device__ __forceinline__ ull f2pack(float lo, float hi) {
    ull r; asm("mov.b64 %0, {%1, %2};" : "=l"(r) : "r"(__float_as_uint(lo)), "r"(__float_as_uint(hi)));
    return r;
}
__device__ __forceinline__ float f2lo(ull v) { return __uint_as_float((unsigned)(v & 0xFFFFFFFFu)); }
__device__ __forceinline__ float f2hi(ull v) { return __uint_as_float((unsigned)(v >> 32)); }

__device__ __forceinline__ uint32_t smem_u32(const void* p) {
    uint32_t a;
    asm("{ .reg .u64 t; cvta.to.shared.u64 t, %1; cvt.u32.u64 %0, t; }" : "=r"(a) : "l"(p));
    return a;
}
__device__ __forceinline__ void ldsm4(uint32_t r[4], uint32_t addr) {
    asm volatile("ldmatrix.sync.aligned.m8n8.x4.shared.b16 {%0,%1,%2,%3}, [%4];"
                 : "=r"(r[0]), "=r"(r[1]), "=r"(r[2]), "=r"(r[3]) : "r"(addr));
}
__device__ __forceinline__ void ldsm4t(uint32_t r[4], uint32_t addr) {
    asm volatile("ldmatrix.sync.aligned.m8n8.x4.trans.shared.b16 {%0,%1,%2,%3}, [%4];"
                 : "=r"(r[0]), "=r"(r[1]), "=r"(r[2]), "=r"(r[3]) : "r"(addr));
}
__device__ __forceinline__ void mma16816(float c[4], const uint32_t a[4],
                                         uint32_t b0, uint32_t b1) {
    asm volatile(
        "mma.sync.aligned.m16n8k16.row.col.f32.bf16.bf16.f32 "
        "{%0,%1,%2,%3}, {%4,%5,%6,%7}, {%8,%9}, {%0,%1,%2,%3};\n"
        : "+f"(c[0]), "+f"(c[1]), "+f"(c[2]), "+f"(c[3])
        : "r"(a[0]), "r"(a[1]), "r"(a[2]), "r"(a[3]), "r"(b0), "r"(b1));
}

// ============================================================
// Kernel 0: one-time fp32 -> bf16 hi/lo conversion of W (x4) and x.
// ============================================================
__global__ __launch_bounds__(256) void convert_kernel(
    const float* __restrict__ x,
    const float* __restrict__ Wl0, const float* __restrict__ Wr0,
    const float* __restrict__ Wl1, const float* __restrict__ Wr1)
{
    pdl_trigger();
    int by = blockIdx.y;
    const float* src;
    __nv_bfloat16 *dh, *dl;
    int limit;
    if (by < 4) {
        src = (by == 0) ? Wl0 : (by == 1) ? Wr0 : (by == 2) ? Wl1 : Wr1;
        dh = d_wbh + by * DD * DD; dl = d_wbl + by * DD * DD; limit = DD * DD;
    } else {
        src = x; dh = d_xbh; dl = d_xbl; limit = NN * DD;
    }
    int e = (blockIdx.x * 256 + threadIdx.x) * 4;
    if (e >= limit) return;
    float4 v = *(const float4*)&src[e];
    __nv_bfloat162 h0, h1, l0, l1;
    h0.x = __float2bfloat16(v.x); h0.y = __float2bfloat16(v.y);
    h1.x = __float2bfloat16(v.z); h1.y = __float2bfloat16(v.w);
    l0.x = __float2bfloat16(v.x - __bfloat162float(h0.x));
    l0.y = __float2bfloat16(v.y - __bfloat162float(h0.y));
    l1.x = __float2bfloat16(v.z - __bfloat162float(h1.x));
    l1.y = __float2bfloat16(v.w - __bfloat162float(h1.y));
    *(__nv_bfloat162*)&dh[e]     = h0;
    *(__nv_bfloat162*)&dh[e + 2] = h1;
    *(__nv_bfloat162*)&dl[e]     = l0;
    *(__nv_bfloat162*)&dl[e + 2] = l1;
}

// ============================================================
// Kernel 1: bf16x3 tensor-core GEMM + fused rank-1 r/l epilogue.
// Layer 1 prefetches W (safe: convert is >=3 nodes back) before pdl_wait.
// ============================================================
__global__ __launch_bounds__(256) void gemm_kernel(int layer, const float* __restrict__ a_vec)
{
    __shared__ __align__(16) __nv_bfloat16 Ah[32][72], Al[32][72];
    __shared__ __align__(16) __nv_bfloat16 Bh[64][72], Bl[64][72];
    __shared__ float red[4][33];

    pdl_trigger();

    int tid = threadIdx.x;
    int bx  = blockIdx.x;
    int i0  = blockIdx.y * 32;
    int isL = (bx < 8);
    int c0  = (bx & 7) * 64;
    int widx = layer * 2 + (isL ? 0 : 1);
    const __nv_bfloat16* A_h = d_xbh + layer * NN * DD;
    const __nv_bfloat16* A_l = d_xbl + layer * NN * DD;
    const __nv_bfloat16* W_h = d_wbh + widx * DD * DD;
    const __nv_bfloat16* W_l = d_wbl + widx * DD * DD;
    float* outp = isL ? d_gl : d_gr;

    int warp = tid >> 5, lane = tid & 31;
    int wm = warp >> 2, wn = warp & 3;

    int ar = tid >> 3, ac = (tid & 7) * 8;
    int br = tid >> 2, bc = (tid & 3) * 16;

    uint32_t aadr_h = smem_u32(&Ah[wm * 16 + (lane & 15)][(lane >> 4) * 8]);
    uint32_t aadr_l = smem_u32(&Al[wm * 16 + (lane & 15)][(lane >> 4) * 8]);
    int bkrow = (lane & 7) + ((lane >> 3) & 1) * 8;
    uint32_t badr_h = smem_u32(&Bh[bkrow][wn * 16 + (lane >> 4) * 8]);
    uint32_t badr_l = smem_u32(&Bl[bkrow][wn * 16 + (lane >> 4) * 8]);

    float c0f[4] = {0,0,0,0};
    float c1f[4] = {0,0,0,0};

    uint4 pah, pal, pbh0, pbh1, pbl0, pbl1;
    if (layer) {
        // W written by convert, >= 3 nodes upstream: already globally visible.
        pbh0 = *(const uint4*)&W_h[br * DD + c0 + bc];
        pbh1 = *(const uint4*)&W_h[br * DD + c0 + bc + 8];
        pbl0 = *(const uint4*)&W_l[br * DD + c0 + bc];
        pbl1 = *(const uint4*)&W_l[br * DD + c0 + bc + 8];
        pdl_wait();
        pah  = *(const uint4*)&A_h[(i0 + ar) * DD + ac];
        pal  = *(const uint4*)&A_l[(i0 + ar) * DD + ac];
    } else {
        pdl_wait();
        pah  = *(const uint4*)&A_h[(i0 + ar) * DD + ac];
        pal  = *(const uint4*)&A_l[(i0 + ar) * DD + ac];
        pbh0 = *(const uint4*)&W_h[br * DD + c0 + bc];
        pbh1 = *(const uint4*)&W_h[br * DD + c0 + bc + 8];
        pbl0 = *(const uint4*)&W_l[br * DD + c0 + bc];
        pbl1 = *(const uint4*)&W_l[br * DD + c0 + bc + 8];
    }

    for (int k0 = 0; k0 < DD; k0 += 64) {
        *(uint4*)&Ah[ar][ac]      = pah;
        *(uint4*)&Al[ar][ac]      = pal;
        *(uint4*)&Bh[br][bc]      = pbh0;
        *(uint4*)&Bh[br][bc + 8]  = pbh1;
        *(uint4*)&Bl[br][bc]      = pbl0;
        *(uint4*)&Bl[br][bc + 8]  = pbl1;
        __syncthreads();

        int kn = k0 + 64;
        if (kn < DD) {
            pah  = *(const uint4*)&A_h[(i0 + ar) * DD + kn + ac];
            pal  = *(const uint4*)&A_l[(i0 + ar) * DD + kn + ac];
            pbh0 = *(const uint4*)&W_h[(kn + br) * DD + c0 + bc];
            pbh1 = *(const uint4*)&W_h[(kn + br) * DD + c0 + bc + 8];
            pbl0 = *(const uint4*)&W_l[(kn + br) * DD + c0 + bc];
            pbl1 = *(const uint4*)&W_l[(kn + br) * DD + c0 + bc + 8];
        }

        #pragma unroll
        for (int kc = 0; kc < 4; kc++) {
            uint32_t ah[4], al[4], bh[4], bl[4];
            ldsm4 (ah, aadr_h + kc * 32);
            ldsm4 (al, aadr_l + kc * 32);
            ldsm4t(bh, badr_h + kc * 16 * 144);
            ldsm4t(bl, badr_l + kc * 16 * 144);
            mma16816(c0f, ah, bh[0], bh[1]);
            mma16816(c0f, al, bh[0], bh[1]);
            mma16816(c0f, ah, bl[0], bl[1]);
            mma16816(c1f, ah, bh[2], bh[3]);
            mma16816(c1f, al, bh[2], bh[3]);
            mma16816(c1f, ah, bl[2], bl[3]);
        }
        __syncthreads();
    }

    int r0 = i0 + wm * 16 + (lane >> 2);
    int r1 = r0 + 8;
    int cb = c0 + wn * 16 + 2 * (lane & 3);
    *(float2*)&outp[r0 * DD + cb]     = make_float2(c0f[0], c0f[1]);
    *(float2*)&outp[r0 * DD + cb + 8] = make_float2(c1f[0], c1f[1]);
    *(float2*)&outp[r1 * DD + cb]     = make_float2(c0f[2], c0f[3]);
    *(float2*)&outp[r1 * DD + cb + 8] = make_float2(c1f[2], c1f[3]);

    int f0 = wn * 16 + 2 * (lane & 3);
    float af0 = a_vec[f0], af1 = a_vec[f0 + 1];
    float af8 = a_vec[f0 + 8], af9 = a_vec[f0 + 9];
    float p0 = af0 * c0f[0] + af1 * c0f[1] + af8 * c1f[0] + af9 * c1f[1];
    float p1 = af0 * c0f[2] + af1 * c0f[3] + af8 * c1f[2] + af9 * c1f[3];
    p0 += __shfl_xor_sync(0xffffffffu, p0, 1);
    p0 += __shfl_xor_sync(0xffffffffu, p0, 2);
    p1 += __shfl_xor_sync(0xffffffffu, p1, 1);
    p1 += __shfl_xor_sync(0xffffffffu, p1, 2);
    if ((lane & 3) == 0) {
        red[wn][wm * 16 + (lane >> 2)]     = p0;
        red[wn][wm * 16 + 8 + (lane >> 2)] = p1;
    }
    __syncthreads();
    if (tid < 32) {
        int h = bx & 7;
        float* dst = isL ? d_lvec : d_rvec;
        dst[h * NN + i0 + tid] = red[0][tid] + red[1][tid] + red[2][tid] + red[3][tid];
    }
}

// ============================================================
// Kernel 2: FUSED attention, 64-j split per block (2 sub-tiles of 32).
// adj mask + a_vec loads run pre-wait (independent of gemm).
// ============================================================
__global__ __launch_bounds__(128) void attn_kernel(
    const float* __restrict__ a_vec, const int* __restrict__ adj)
{
    __shared__ __align__(16) float gri[32 * 64];
    __shared__ __align__(16) float buf[32 * 66];
    __shared__ __align__(16) float ew[32 * 65];
    __shared__ __align__(16) float as[64];
    __shared__ float rvs[32], lvs[64];
    __shared__ float redm[4][32], reds[4][32];

    pdl_trigger();

    int tid = threadIdx.x;
    int i0 = blockIdx.x * 32;
    int h  = blockIdx.y;
    int s  = blockIdx.z;
    int jb = s * 64;

    // ---- independent prologue: a_vec + adjacency masks ----
    if (tid < 64) as[tid] = a_vec[tid];

    int jj = tid & 31;
    int ib = tid >> 5;
    int mk[2][8];
    #pragma unroll
    for (int jt = 0; jt < 2; jt++)
        #pragma unroll
        for (int q = 0; q < 8; q++) {
            int i = i0 + ib + q * 4;
            int j = jb + jt * 32 + jj;
            mk[jt][q] = (adj[i * NN + j] != 0) || (i == j);
        }

    pdl_wait();

    if (tid < 64)       lvs[tid]      = d_lvec[h * NN + jb + tid];
    else if (tid < 96)  rvs[tid - 64] = d_rvec[h * NN + i0 + (tid - 64)];

    #pragma unroll
    for (int p = 0; p < 4; p++) {
        int idx = tid + p * 128;
        int r = idx >> 4, f4 = (idx & 15) * 4;
        *(float4*)&gri[r * 64 + f4] = *(const float4*)&d_gr[(i0 + r) * DD + h * FF + f4];
    }

    // ---- phase 1: logits, two 32-j sub-tiles through shared buf ----
    #pragma unroll 1
    for (int jt = 0; jt < 2; jt++) {
        __syncthreads();
        #pragma unroll
        for (int p = 0; p < 4; p++) {
            int idx = tid + p * 128;
            int r = idx >> 4, f4 = (idx & 15) * 4;
            float4 w = *(const float4*)&d_gl[(jb + jt * 32 + r) * DD + h * FF + f4];
            *(float2*)&buf[r * 66 + f4]     = make_float2(w.x, w.y);
            *(float2*)&buf[r * 66 + f4 + 2] = make_float2(w.z, w.w);
        }
        __syncthreads();

        ull accp[8] = {0,0,0,0,0,0,0,0};
        #pragma unroll 8
        for (int f = 0; f < 64; f += 2) {
            ull gl2 = *(const ull*)&buf[jj * 66 + f];
            ull a2  = *(const ull*)&as[f];
            #pragma unroll
            for (int q = 0; q < 8; q++) {
                ull v = f2add(*(const ull*)&gri[(ib + q * 4) * 64 + f], gl2);
                v &= 0x7FFFFFFF7FFFFFFFULL;
                accp[q] = f2fma(a2, v, accp[q]);
            }
        }
        float lvj = lvs[jt * 32 + jj];
        #pragma unroll
        for (int q = 0; q < 8; q++) {
            int il = ib + q * 4;
            float sum = f2lo(accp[q]) + f2hi(accp[q]);
            float e = 0.6f * (rvs[il] + lvj) + 0.4f * sum;
            ew[il * 65 + jt * 32 + jj] = mk[jt][q] ? e : -1e30f;
        }
    }
    __syncthreads();

    // ---- phase 2: per-row stats over 64 j + exp in place ----
    int r  = tid & 31;
    int qd = tid >> 5;
    float pm = -1e38f;
    #pragma unroll
    for (int jn = 0; jn < 16; jn++) pm = fmaxf(pm, ew[r * 65 + qd * 16 + jn]);
    redm[qd][r] = pm;
    __syncthreads();
    float M = fmaxf(fmaxf(redm[0][r], redm[1][r]), fmaxf(redm[2][r], redm[3][r]));
    float ssum = 0.f;
    #pragma unroll
    for (int jn = 0; jn < 16; jn++) {
        int ix = r * 65 + qd * 16 + jn;
        float w = __expf(ew[ix] - M);
        ew[ix] = w;
        ssum += w;
    }
    reds[qd][r] = ssum;
    __syncthreads();
    if (qd == 0) {
        d_pm[(s * HH + h) * NN + i0 + r] = M;
        d_ps[(s * HH + h) * NN + i0 + r] = reds[0][r] + reds[1][r] + reds[2][r] + reds[3][r];
    }

    // ---- phase 3: aggregation over 64 j, grj through shared buf ----
    int ib2 = tid >> 4;
    int f   = (tid & 15) * 4;
    ull acc0[4] = {0,0,0,0}, acc1[4] = {0,0,0,0};
    #pragma unroll 1
    for (int jt = 0; jt < 2; jt++) {
        #pragma unroll
        for (int p = 0; p < 4; p++) {
            int idx = tid + p * 128;
            int rr = idx >> 4, f4 = (idx & 15) * 4;
            *(float4*)&buf[rr * 64 + f4] =
                *(const float4*)&d_gr[(jb + jt * 32 + rr) * DD + h * FF + f4];
        }
        __syncthreads();
        #pragma unroll
        for (int j2 = 0; j2 < 32; j2++) {
            ull g01 = *(const ull*)&buf[j2 * 64 + f];
            ull g23 = *(const ull*)&buf[j2 * 64 + f + 2];
            #pragma unroll
            for (int q = 0; q < 4; q++) {
                float w = ew[(ib2 + q * 8) * 65 + jt * 32 + j2];
                ull ww = f2pack(w, w);
                acc0[q] = f2fma(ww, g01, acc0[q]);
                acc1[q] = f2fma(ww, g23, acc1[q]);
            }
        }
        __syncthreads();
    }
    #pragma unroll
    for (int q = 0; q < 4; q++) {
        int i = i0 + ib2 + q * 8;
        *(float4*)&d_part[(s * NN + i) * DD + h * FF + f] =
            make_float4(f2lo(acc0[q]), f2hi(acc0[q]), f2lo(acc1[q]), f2hi(acc1[q]));
    }
}

// ============================================================
// Kernel 3: finalize. Per-thread redundant coef computation (no smem, no
// syncthreads). Grid (48, 8) x 128 thr. Residual + optional ELU.
// xin is always >= 3 nodes upstream -> loaded pre-wait.
// ============================================================
__global__ __launch_bounds__(128) void finalize_kernel(
    const float* __restrict__ xin_ext, int use_x1_in,
    float* __restrict__ out_ext, int write_x1, int do_elu)
{
    pdl_trigger();

    const float* xin  = use_x1_in ? d_x1 : xin_ext;
    float*       outp = write_x1  ? d_x1 : out_ext;

    int tid = threadIdx.x;
    int i0 = blockIdx.x * 8;
    int h  = blockIdx.y;

    int il = tid >> 4;
    int f4 = (tid & 15) * 4;
    int i  = i0 + il;
    int base = i * DD + h * FF + f4;

    float4 xa = *(const float4*)&xin[base];   // input or d_x1 (3 nodes back): safe

    pdl_wait();

    // per-thread softmax-combine coefficients (broadcast loads, L1-resident)
    float m[SPL], ps[SPL];
    #pragma unroll
    for (int s2 = 0; s2 < SPL; s2++) {
        m[s2]  = d_pm[(s2 * HH + h) * NN + i];
        ps[s2] = d_ps[(s2 * HH + h) * NN + i];
    }
    float M = m[0];
    #pragma unroll
    for (int s2 = 1; s2 < SPL; s2++) M = fmaxf(M, m[s2]);
    float c[SPL], D = 0.f;
    #pragma unroll
    for (int s2 = 0; s2 < SPL; s2++) {
        c[s2] = __expf(m[s2] - M);
        D = fmaf(ps[s2], c[s2], D);
    }
    float invD = 1.f / D;

    float4 A = {0,0,0,0};
    #pragma unroll
    for (int s2 = 0; s2 < SPL; s2++) {
        float cc = c[s2] * invD;
        float4 p = *(const float4*)&d_part[(s2 * NN + i) * DD + h * FF + f4];
        A.x = fmaf(cc, p.x, A.x); A.y = fmaf(cc, p.y, A.y);
        A.z = fmaf(cc, p.z, A.z); A.w = fmaf(cc, p.w, A.w);
    }
    if (do_elu) {
        A.x = A.x > 0.f ? A.x : expm1f(A.x);
        A.y = A.y > 0.f ? A.y : expm1f(A.y);
        A.z = A.z > 0.f ? A.z : expm1f(A.z);
        A.w = A.w > 0.f ? A.w : expm1f(A.w);
    }
    float4 oA = make_float4(xa.x + A.x, xa.y + A.y, xa.z + A.z, xa.w + A.w);
    *(float4*)&outp[base] = oA;

    if (write_x1) {
        __nv_bfloat16* xh = d_xbh + NN * DD;
        __nv_bfloat16* xl = d_xbl + NN * DD;
        __nv_bfloat162 h0, h1, l0, l1;
        h0.x = __float2bfloat16(oA.x); h0.y = __float2bfloat16(oA.y);
        h1.x = __float2bfloat16(oA.z); h1.y = __float2bfloat16(oA.w);
        l0.x = __float2bfloat16(oA.x - __bfloat162float(h0.x));
        l0.y = __float2bfloat16(oA.y - __bfloat162float(h0.y));
        l1.x = __float2bfloat16(oA.z - __bfloat162float(h1.x));
        l1.y = __float2bfloat16(oA.w - __bfloat162float(h1.y));
        *(__nv_bfloat162*)&xh[base]     = h0;
        *(__nv_bfloat162*)&xh[base + 2] = h1;
        *(__nv_bfloat162*)&xl[base]     = l0;
        *(__nv_bfloat162*)&xl[base + 2] = l1;
    }
}

// ============================================================
extern "C" void kernel_launch(void* const* d_in, const int* in_sizes, int n_in,
                              void* d_out, int out_size)
{
    const float* x   = (const float*)d_in[0];
    const int*   adj = (const int*)  d_in[1];
    const float* Wl0 = (const float*)d_in[2];
    const float* Wr0 = (const float*)d_in[3];
    const float* a0  = (const float*)d_in[4];
    const float* Wl1 = (const float*)d_in[5];
    const float* Wr1 = (const float*)d_in[6];
    const float* a1  = (const float*)d_in[7];
    float* out = (float*)d_out;

    cudaLaunchAttribute attr[1];
    attr[0].id = cudaLaunchAttributeProgrammaticStreamSerialization;
    attr[0].val.programmaticStreamSerializationAllowed = 1;

    cudaLaunchConfig_t cfg{};
    cfg.attrs = attr;
    cfg.numAttrs = 1;
    cfg.stream = 0;

    // convert
    cfg.gridDim = dim3(256, 5); cfg.blockDim = dim3(256);
    cudaLaunchKernelEx(&cfg, convert_kernel, x, Wl0, Wr0, Wl1, Wr1);

    // ---- layer 0 ----
    cfg.gridDim = dim3(16, 12); cfg.blockDim = dim3(256);
    cudaLaunchKernelEx(&cfg, gemm_kernel, 0, a0);
    cfg.gridDim = dim3(12, 8, SPL); cfg.blockDim = dim3(128);
    cudaLaunchKernelEx(&cfg, attn_kernel, a0, adj);
    cfg.gridDim = dim3(48, 8); cfg.blockDim = dim3(128);
    cudaLaunchKernelEx(&cfg, finalize_kernel, x, 0, (float*)nullptr, 1, 1);

    // ---- layer 1 ----
    cfg.gridDim = dim3(16, 12); cfg.blockDim = dim3(256);
    cudaLaunchKernelEx(&cfg, gemm_kernel, 1, a1);
    cfg.gridDim = dim3(12, 8, SPL); cfg.blockDim = dim3(128);
    cudaLaunchKernelEx(&cfg, attn_kernel, a1, adj);
    cfg.gridDim = dim3(48, 8); cfg.blockDim = dim3(128);
    cudaLaunchKernelEx(&cfg, finalize_kernel, (const float*)nullptr, 1, out, 0, 0);
}